// round 17
// baseline (speedup 1.0000x reference)
#include <cuda_runtime.h>
#include <cuda.h>
#include <math.h>

#define N_ROWS 1024
#define RANK   8
#define M_LEN  8192
#define TPB    256
#define NB     2             // n rows per main block
#define MCH    2048          // m-chunk per main block
#define JP     4             // j steps (each covers 2 m at stride 512)
#define NSUB   16            // FFT decimation factor
#define LSUB   512           // sub-FFT length

// Device globals (allocation forbidden)
__device__ __align__(16) float2 snmf23_Hf[RANK * M_LEN];
__device__ __align__(16) float2 snmf23_S [RANK * M_LEN];  // sub-FFT results

__device__ __forceinline__ int snmf23_iclamp(int i, int cap) {
    return min(i, cap - 1);
}

// ---- packed f32x2 helpers (FFMA2 is PTX-only; ptxas won't auto-fuse) ----
__device__ __forceinline__ unsigned long long snmf23_pk2(float lo, float hi) {
    unsigned long long r;
    asm("mov.b64 %0, {%1, %2};" : "=l"(r) : "f"(lo), "f"(hi));
    return r;
}
__device__ __forceinline__ float2 snmf23_upk2(unsigned long long v) {
    float lo, hi;
    asm("mov.b64 {%0, %1}, %2;" : "=f"(lo), "=f"(hi) : "l"(v));
    return make_float2(lo, hi);
}
__device__ __forceinline__ unsigned long long snmf23_fma2(
    unsigned long long a, unsigned long long b, unsigned long long c) {
    unsigned long long r;
    asm("fma.rn.f32x2 %0, %1, %2, %3;" : "=l"(r) : "l"(a), "l"(b), "l"(c));
    return r;
}
__device__ __forceinline__ unsigned long long snmf23_mul2(
    unsigned long long a, unsigned long long b) {
    unsigned long long r;
    asm("mul.rn.f32x2 %0, %1, %2;" : "=l"(r) : "l"(a), "l"(b));
    return r;
}

// ---------------------------------------------------------------------------
// Kernel F1: 128 blocks (row, s). Each: 512-pt FFT of x_s[t] = sp(H[16t+s]).
// ---------------------------------------------------------------------------
__global__ __launch_bounds__(TPB) void snmf23_fft1_k(const float* __restrict__ H,
                                                     int h_cap) {
    __shared__ float2 Z[LSUB];      // 4KB
    __shared__ float2 Wt[256];      // 2KB: Wt[q] = exp(-iπ q/256)
    const int row = blockIdx.x >> 4;
    const int s   = blockIdx.x & 15;
    const int tid = threadIdx.x;
    const int base = row * M_LEN;

    if (tid < 256) {
        float sn, cs;
        sincospif(-(float)tid / 256.0f, &sn, &cs);
        Wt[tid] = make_float2(cs, sn);
    }
    for (int t = tid; t < LSUB; t += TPB) {
        unsigned rb = __brev((unsigned)t) >> 23;   // 9-bit reversal
        float x = H[snmf23_iclamp(base + 16 * t + s, h_cap)];
        Z[rb] = make_float2(log1pf(expf(x)), 0.0f);
    }
    __syncthreads();

    #pragma unroll 1
    for (int st = 1; st <= 9; st++) {
        const int half = 1 << (st - 1);
        {
            int k = tid;                           // 256 butterflies, 1/thread
            int grp = k >> (st - 1);
            int jj  = k & (half - 1);
            int i1  = (grp << st) + jj;
            int i2  = i1 + half;
            float2 tw = Wt[jj << (9 - st)];
            float2 a = Z[i1], b = Z[i2];
            float tr = tw.x * b.x - tw.y * b.y;
            float ti = tw.x * b.y + tw.y * b.x;
            Z[i2] = make_float2(a.x - tr, a.y - ti);
            Z[i1] = make_float2(a.x + tr, a.y + ti);
        }
        __syncthreads();
    }

    for (int k = tid; k < LSUB; k += TPB)
        snmf23_S[(row * NSUB + s) * LSUB + k] = Z[k];
}

// ---------------------------------------------------------------------------
// Kernel F2: combine. X[k] = Σ_s (e^{-2πik/8192})^s · S_s[k mod 512].
// ---------------------------------------------------------------------------
__global__ __launch_bounds__(TPB) void snmf23_fft2_k() {
    const int gid = blockIdx.x * TPB + threadIdx.x;   // 0..65535
    const int row = gid >> 13;
    const int k   = gid & (M_LEN - 1);
    const int kr  = k & (LSUB - 1);

    const float2* Sp = snmf23_S + row * M_LEN + kr;
    float sn, cs;
    sincospif(-(float)k / 4096.0f, &sn, &cs);         // e^{-2πik/8192}
    float2 acc = Sp[0];
    float wr = cs, wi = sn;
    #pragma unroll
    for (int s = 1; s < NSUB; s++) {
        float2 v = Sp[s << 9];
        acc.x = fmaf(wr, v.x, fmaf(-wi, v.y, acc.x));
        acc.y = fmaf(wr, v.y, fmaf( wi, v.x, acc.y));
        float nwr = fmaf(wr, cs, -wi * sn);
        float nwi = fmaf(wr, sn,  wi * cs);
        wr = nwr; wi = nwi;
    }
    snmf23_Hf[row * M_LEN + k] = acc;
}

// ---------------------------------------------------------------------------
// Kernel M: main reduction, packed f32x2 hot loop.
// Thread owns m = m0 + 2*tid + j*512 + {0,1}. Packed lanes = the two m's.
// ---------------------------------------------------------------------------
__global__ __launch_bounds__(TPB) void snmf23_main_k(
    const float* __restrict__ pa, int ca,
    const float* __restrict__ pb, int cb,
    float* __restrict__ out, long long out_cap)
{
    __shared__ float2 sdl[NB][RANK];   // delta512 = exp(-2πi τ·512/M)
    __shared__ float2 sd1[NB][RANK];   // d1      = exp(-2πi τ/M)
    __shared__ float  sc [NB][RANK];   // softmax coef
    __shared__ float  st [NB][RANK];   // tau

    const int tid = threadIdx.x;
    const int m0  = blockIdx.x * MCH;
    const int n0  = blockIdx.y * NB;

    // inline decide: candidate with negatives is tau
    int negA = (pa[snmf23_iclamp(tid, ca)] < -0.01f) ? 1 : 0;
    int aIsTau = __syncthreads_or(negA);
    const float* Wp = aIsTau ? pb : pa;  const int w_cap = aIsTau ? cb : ca;
    const float* Tp = aIsTau ? pa : pb;  const int t_cap = aIsTau ? ca : cb;

    // inline prep: 16 threads fill (nn, r) tables
    if (tid < NB * RANK) {
        const int nn = tid >> 3, r = tid & 7;
        const int n  = n0 + nn;
        float wv[RANK];
        float mx = -INFINITY;
        #pragma unroll
        for (int k = 0; k < RANK; k++) {
            wv[k] = Wp[snmf23_iclamp(n * RANK + k, w_cap)];
            mx = fmaxf(mx, wv[k]);
        }
        float sum = 0.0f;
        #pragma unroll
        for (int k = 0; k < RANK; k++) sum += expf(wv[k] - mx);
        float coef = expf(wv[r] - mx) / sum;
        float t = Tp[snmf23_iclamp(n * RANK + r, t_cap)];
        float sn, cs;
        sincospif(-t / 8.0f, &sn, &cs);        // exp(-2πi τ·512/8192)
        sdl[nn][r] = make_float2(cs, sn);
        sincospif(-t / 4096.0f, &sn, &cs);     // exp(-2πi τ/8192)
        sd1[nn][r] = make_float2(cs, sn);
        sc[nn][r] = coef;
        st[nn][r] = t;
    }
    __syncthreads();

    const int   mbase = m0 + 2 * tid;
    const float mbf   = (float)mbase;

    unsigned long long AX[NB][JP];
    #pragma unroll
    for (int nn = 0; nn < NB; nn++)
        #pragma unroll
        for (int j = 0; j < JP; j++) AX[nn][j] = 0ull;

    #pragma unroll 1
    for (int r = 0; r < RANK; r++) {
        unsigned long long WR[NB], WIN[NB], DR[NB], DI[NB], DIN[NB];
        #pragma unroll
        for (int nn = 0; nn < NB; nn++) {
            float2 dl = sdl[nn][r], d1 = sd1[nn][r];
            float sn, cs;
            sincospif(st[nn][r] * mbf * (-2.0f / (float)M_LEN), &sn, &cs);
            float war = sc[nn][r] * cs, wai = sc[nn][r] * sn;
            float wbr = war * d1.x - wai * d1.y;   // ω(m+1) = ω(m)·δ1
            float wbi = war * d1.y + wai * d1.x;
            WR [nn] = snmf23_pk2(war,  wbr);
            WIN[nn] = snmf23_pk2(-wai, -wbi);
            DR [nn] = snmf23_pk2(dl.x,  dl.x);
            DI [nn] = snmf23_pk2(dl.y,  dl.y);
            DIN[nn] = snmf23_pk2(-dl.y, -dl.y);
        }
        const float4* hp4 = (const float4*)(snmf23_Hf + r * M_LEN + mbase);
        #pragma unroll
        for (int j = 0; j < JP; j++) {
            float4 h = hp4[j * 256];               // (hx0,hy0,hx1,hy1)
            unsigned long long HX = snmf23_pk2(h.x, h.z);
            unsigned long long HY = snmf23_pk2(h.y, h.w);
            #pragma unroll
            for (int nn = 0; nn < NB; nn++) {
                // AX += WR·HX + WIN·HY    (Re(ω·Hf), both m-lanes at once)
                AX[nn][j] = snmf23_fma2(WR[nn], HX,
                             snmf23_fma2(WIN[nn], HY, AX[nn][j]));
                // chain advance by δ512:
                //   WR'  = DR·WR + DI·WIN   (= DR·WR − DI·WI)
                //   WIN' = DR·WIN + DIN·WR  (= −(DR·WI + DI·WR))
                unsigned long long nWR =
                    snmf23_fma2(DR[nn], WR[nn],  snmf23_mul2(DI[nn],  WIN[nn]));
                unsigned long long nWIN =
                    snmf23_fma2(DR[nn], WIN[nn], snmf23_mul2(DIN[nn], WR[nn]));
                WR[nn] = nWR; WIN[nn] = nWIN;
            }
        }
    }

    #pragma unroll
    for (int nn = 0; nn < NB; nn++) {
        const long long ob = (long long)(n0 + nn) * M_LEN + mbase;
        #pragma unroll
        for (int j = 0; j < JP; j++) {
            long long oi = ob + (long long)j * 512;
            float2 v = snmf23_upk2(AX[nn][j]);     // [ax(m), ax(m+1)]
            if (oi + 1 < out_cap)
                *(float2*)(out + oi) = v;
            else if (oi < out_cap)
                out[oi] = v.x;
        }
    }
}

// ---------------------------------------------------------------------------
// Host: H by self-extent argmax; W/tau disambiguated on-device.  (proven)
// ---------------------------------------------------------------------------
typedef CUresult (CUDAAPI *snmf23_ptr_attr_fn)(void*, CUpointer_attribute, CUdeviceptr);

struct snmf23_range { long long start, size; bool ok; };

static snmf23_range snmf23_get_range(const void* p, snmf23_ptr_attr_fn fn) {
    snmf23_range r; r.start = 0; r.size = -1; r.ok = false;
    if (!fn || !p) return r;
    CUdeviceptr dp = (CUdeviceptr)(uintptr_t)p;
    size_t rsize = 0; CUdeviceptr rstart = 0;
    if (fn(&rsize,  CU_POINTER_ATTRIBUTE_RANGE_SIZE,       dp) != CUDA_SUCCESS) return r;
    if (fn(&rstart, CU_POINTER_ATTRIBUTE_RANGE_START_ADDR, dp) != CUDA_SUCCESS) return r;
    if (dp < rstart || dp >= rstart + rsize) return r;
    r.start = (long long)rstart; r.size = (long long)rsize; r.ok = true;
    return r;
}

extern "C" void kernel_launch(void* const* d_in, const int* in_sizes, int n_in,
                              void* d_out, int out_size) {
    if (n_in < 3 || !d_out) return;

    snmf23_ptr_attr_fn attr = nullptr;
    {
        void* fp = nullptr;
        cudaDriverEntryPointQueryResult qr;
        if (cudaGetDriverEntryPoint("cuPointerGetAttribute", &fp,
                                    cudaEnableDefault, &qr) == cudaSuccess)
            attr = (snmf23_ptr_attr_fn)fp;
    }

    const float* p[3]; long long addr[3]; snmf23_range rg[3];
    for (int i = 0; i < 3; i++) {
        p[i]    = (const float*)d_in[i];
        addr[i] = (long long)(uintptr_t)d_in[i];
        rg[i]   = snmf23_get_range(d_in[i], attr);
    }

    int cap[3];
    for (int i = 0; i < 3; i++) {
        long long avail = -1;
        if (rg[i].ok) avail = (rg[i].start + rg[i].size - addr[i]) / 4;
        long long c = RANK * M_LEN;
        if (avail > 0) c = (avail < c) ? avail : c;
        else if (in_sizes[i] > 0 && in_sizes[i] < c) c = in_sizes[i];
        cap[i] = (int)((c < 1) ? 1 : c);
    }

    long long se[3];
    for (int i = 0; i < 3; i++) {
        if (rg[i].ok) {
            long long lim = rg[i].start + rg[i].size;
            for (int j = 0; j < 3; j++) {
                if (j == i) continue;
                if (rg[j].ok && rg[j].start == rg[i].start &&
                    addr[j] > addr[i] && addr[j] < lim)
                    lim = addr[j];
            }
            se[i] = lim - addr[i];
        } else {
            se[i] = (long long)in_sizes[i] * 4;
        }
    }

    int hi = 0;
    for (int i = 1; i < 3; i++) if (se[i] > se[hi]) hi = i;
    int ia = -1, ib = -1;
    for (int i = 0; i < 3; i++) {
        if (i == hi) continue;
        if (ia < 0) ia = i; else ib = i;
    }

    long long ob = -1;
    {
        snmf23_range ro = snmf23_get_range(d_out, attr);
        if (ro.ok) ob = (ro.start + ro.size - (long long)(uintptr_t)d_out);
    }
    long long out_cap = (long long)N_ROWS * M_LEN;      // 8388608 floats
    if (out_size > 0 && (long long)out_size < out_cap) out_cap = out_size;
    if (ob > 0 && ob / 4 < out_cap) out_cap = ob / 4;
    if (out_cap < 1) return;

    float* out = (float*)d_out;

    snmf23_fft1_k<<<RANK * NSUB, TPB>>>(p[hi], cap[hi]);
    snmf23_fft2_k<<<(RANK * M_LEN) / TPB, TPB>>>();
    snmf23_main_k<<<dim3(M_LEN / MCH, N_ROWS / NB), TPB>>>(
        p[ia], cap[ia], p[ib], cap[ib], out, out_cap);
}